// round 15
// baseline (speedup 1.0000x reference)
#include <cuda_runtime.h>
#include <cuda_fp16.h>
#include <math.h>

typedef unsigned u32;
typedef unsigned long long u64;

#define TE 128

// Pre-swizzled fp16 W2 tile images: [ktile(2)][chunk(8)][128n x 128k fp16 = 32KB]
__device__ __align__(16) __half g_B[2][8][16384];

// ---------------- helpers ----------------
__device__ __forceinline__ u32 smem_u32(const void* p) {
    u32 a; asm("{ .reg .u64 t; cvta.to.shared.u64 t, %1; cvt.u32.u64 %0, t; }" : "=r"(a) : "l"(p));
    return a;
}
__device__ __forceinline__ void cp16(u32 dst, const void* src) {
    asm volatile("cp.async.cg.shared.global [%0], [%1], 16;" :: "r"(dst), "l"(src));
}
__device__ __forceinline__ void cp_commit() { asm volatile("cp.async.commit_group;"); }
template<int N> __device__ __forceinline__ void cp_wait() {
    asm volatile("cp.async.wait_group %0;" :: "n"(N));
}
__device__ __forceinline__ void ldsm4(u32* r, u32 addr) {
    asm volatile("ldmatrix.sync.aligned.m8n8.x4.shared.b16 {%0,%1,%2,%3}, [%4];"
        : "=r"(r[0]), "=r"(r[1]), "=r"(r[2]), "=r"(r[3]) : "r"(addr));
}
__device__ __forceinline__ void mma16816(float* d, const u32* a, u32 b0, u32 b1) {
    asm volatile("mma.sync.aligned.m16n8k16.row.col.f32.f16.f16.f32 "
        "{%0,%1,%2,%3}, {%4,%5,%6,%7}, {%8,%9}, {%0,%1,%2,%3};"
        : "+f"(d[0]), "+f"(d[1]), "+f"(d[2]), "+f"(d[3])
        : "r"(a[0]), "r"(a[1]), "r"(a[2]), "r"(a[3]), "r"(b0), "r"(b1));
}

#define MBARRIER_INIT(mbar, count) \
    asm volatile("mbarrier.init.shared.b64 [%0], %1;" :: "r"((u32)(mbar)), "r"((u32)(count)) : "memory")
#define MBARRIER_EXPECT_TX(mbar, tx) \
    asm volatile("mbarrier.arrive.expect_tx.shared.b64 _, [%0], %1;" :: "r"((u32)(mbar)), "r"((u32)(tx)) : "memory")
#define MBARRIER_ARRIVE(mbar) \
    asm volatile("mbarrier.arrive.shared.b64 _, [%0];" :: "r"((u32)(mbar)) : "memory")
#define MBARRIER_WAIT_PARITY(mbar, parity) do { \
    u32 _mb = (u32)(mbar); u32 _pa = (u32)(parity); u32 _done; \
    asm volatile("{\n\t.reg .pred p;\n\t" \
        "mbarrier.try_wait.parity.acquire.cta.shared::cta.b64 p, [%1], %2;\n\t" \
        "selp.b32 %0, 1, 0, p;\n\t}" : "=r"(_done) : "r"(_mb), "r"(_pa) : "memory"); \
    if (!_done) { \
        asm volatile("{\n\t.reg .pred P1;\n\t" \
            "WAIT_LOOP_%=:\n\t" \
            "mbarrier.try_wait.parity.acquire.cta.shared::cta.b64 P1, [%0], %1, 0x989680;\n\t" \
            "@P1 bra.uni WAIT_DONE_%=;\n\t" \
            "bra.uni WAIT_LOOP_%=;\n\t" \
            "WAIT_DONE_%=:\n\t}" :: "r"(_mb), "r"(_pa) : "memory"); \
    } \
} while (0)

#define BULK_G2S(dst, src, bytes, mbar) \
    asm volatile("cp.async.bulk.shared::cluster.global.mbarrier::complete_tx::bytes [%0], [%1], %2, [%3];" \
        :: "r"((u32)(dst)), "l"(src), "r"((u32)(bytes)), "r"((u32)(mbar)) : "memory")

// ---------------- smem layout ----------------
// bytes:
#define RING_B 0          // 3 slots x 32768
#define HS_B   98304      // A image: 128 edges x 256 k fp16 = 64KB (512B rows)
// transient constants alias ring slot 2 (base byte 65536 = float 16384):
#define W1S_F  16384      // [18][256]
#define B1S_F  20992      // 256
#define EMBS_F 21248      // 128*18
// persistent floats after HS (byte 163840 = float 40960)
#define B2S_F  40960      // 1024
#define LSS_F  41984      // 128*16
#define LVV_F  44032
#define LSV_F  46080
#define LVS_F  48128      // 128*48
#define Y1_F   54272      // 128*4
#define MB_B   217600     // full[3], empty[3], hdone
#define SMEM_BYTES 219136

// ---------------- prep: fp16 convert + swizzle W2 ----------------
__global__ void prep_w2(const float* __restrict__ W2) {
    int idx = blockIdx.x * blockDim.x + threadIdx.x;
    if (idx >= 256 * 1024) return;
    int k = idx >> 10, n = idx & 1023;
    __half v = __float2half(W2[idx]);
    int kt = k >> 7, kl = k & 127, chunk = n >> 7, nl = n & 127;
    int off = nl * 256 + (((kl >> 3) ^ (nl & 7)) << 4) + (kl & 7) * 2;  // bytes
    g_B[kt][chunk][off >> 1] = v;
}

// ---------------- h compute (full K=256, fp16 out, 512 consumer threads) ----------------
__device__ __forceinline__ void compute_h(float* smf, char* smem, int tid) {
    const int e = tid & 127;
    const int qt = tid >> 7;           // column quarter (64 cols each)
    float er[18];
    #pragma unroll
    for (int t = 0; t < 18; t++) er[t] = smf[EMBS_F + e * 18 + t];
    const int cbase = qt * 64;
    #pragma unroll 2
    for (int cc = 0; cc < 64; cc += 2) {
        const int c = cbase + cc;              // k in [0,256)
        float h[2];
        #pragma unroll
        for (int u = 0; u < 2; u++) {
            float a = smf[B1S_F + c + u];
            #pragma unroll
            for (int t = 0; t < 18; t++)
                a = fmaf(er[t], smf[W1S_F + t * 256 + c + u], a);
            h[u] = a / (1.f + __expf(-a));
        }
        __half2 hp; hp.x = __float2half(h[0]); hp.y = __float2half(h[1]);
        u32 off = (u32)(e * 512 + (((c >> 3) ^ (e & 7)) << 4) + (c & 7) * 2);
        *(u32*)(smem + HS_B + off) = *(u32*)&hp;
    }
}

// ---------------- main kernel: 16 consumer warps (4m x 2n x 2kt) + producer ----------------
__global__ __launch_bounds__(544, 1)
void nequip_mma(const float* __restrict__ nodef,
                const float* __restrict__ eattr,
                const float* __restrict__ eemb,
                const float* __restrict__ W1,
                const float* __restrict__ bias1,
                const float* __restrict__ b2,
                const int* __restrict__ esrc,
                const int* __restrict__ edst,
                float* __restrict__ out,
                int E, float scl)
{
    extern __shared__ char smem[];
    float* smf = (float*)smem;
    const u32 sb = smem_u32(smem);
    const int tid = threadIdx.x;
    const int wid = tid >> 5, lane = tid & 31;
    const int eb = blockIdx.x * TE;
    const u32 mb_full  = sb + MB_B;        // 3 x 8B
    const u32 mb_empty = sb + MB_B + 24;   // 3 x 8B
    const u32 mb_hdone = sb + MB_B + 48;   // 1 x 8B

    // ---- stage constants via cp.async (W1/b1/emb alias ring slot 2) ----
    {
        const u32 w1dst = sb + W1S_F * 4;
        for (int i = tid; i < 1152; i += 544) cp16(w1dst + i * 16, (const char*)W1 + i * 16);
        if (tid < 64) cp16(sb + B1S_F * 4 + tid * 16, (const char*)bias1 + tid * 16);
        if (tid < 256) cp16(sb + B2S_F * 4 + tid * 16, (const char*)b2 + tid * 16);
        if (eb + TE <= E) {
            const u32 emdst = sb + EMBS_F * 4;
            const char* emsrc = (const char*)(eemb + (size_t)eb * 18);
            for (int i = tid; i < 576; i += 544) cp16(emdst + i * 16, emsrc + i * 16);
        } else {
            for (int i = tid; i < TE * 18; i += 544) {
                int g = eb * 18 + i;
                smf[EMBS_F + i] = (g < E * 18) ? eemb[g] : 0.f;
            }
        }
        cp_commit();
    }

    // ---- per-edge left vectors (4 groups of 4 i's; threads 0..511) ----
    if (tid < 512) {
        const int wgtid = tid & 127, wg = tid >> 7;
        const int eg = eb + wgtid;
        if (eg < E) {
            const float inv3 = 0.57735026918962576451f;
            int src = esrc[eg];
            const float* x = nodef + (size_t)src * 64;
            float4 ya = *(const float4*)(eattr + (size_t)eg * 4);
            if (wg == 0) {
                smf[Y1_F + wgtid*4 + 0] = ya.y;
                smf[Y1_F + wgtid*4 + 1] = ya.z;
                smf[Y1_F + wgtid*4 + 2] = ya.w;
            }
            float4 sv = *(const float4*)(x + wg * 4);
            float s4[4] = {sv.x, sv.y, sv.z, sv.w};
            float vv[12];
            const float4* vx = (const float4*)(x + 16 + wg * 12);
            #pragma unroll
            for (int q = 0; q < 3; q++) {
                float4 t = vx[q];
                vv[q*4] = t.x; vv[q*4+1] = t.y; vv[q*4+2] = t.z; vv[q*4+3] = t.w;
            }
            #pragma unroll
            for (int il = 0; il < 4; il++) {
                int i = wg * 4 + il;
                smf[LSS_F + wgtid*16 + i] = ya.x * s4[il];
                smf[LSV_F + wgtid*16 + i] = s4[il];
                smf[LVV_F + wgtid*16 + i] =
                    inv3 * (ya.y*vv[il*3] + ya.z*vv[il*3+1] + ya.w*vv[il*3+2]);
                smf[LVS_F + wgtid*48 + i*3 + 0] = ya.x * vv[il*3 + 0];
                smf[LVS_F + wgtid*48 + i*3 + 1] = ya.x * vv[il*3 + 1];
                smf[LVS_F + wgtid*48 + i*3 + 2] = ya.x * vv[il*3 + 2];
            }
        }
    }

    // ---- init barriers ----
    if (tid == 0) {
        #pragma unroll
        for (int s = 0; s < 3; s++) {
            MBARRIER_INIT(mb_full + s*8, 1);    // producer expect_tx arrival
            MBARRIER_INIT(mb_empty + s*8, 8);   // the 8 reader warps of each tile
        }
        MBARRIER_INIT(mb_hdone, 16);            // all consumer warps after compute_h
        asm volatile("fence.proxy.async.shared::cta;" ::: "memory");
    }
    cp_wait<0>();
    __syncthreads();      // constants visible, barriers initialized

    if (wid == 16) {
        // ================= producer =================
        if (lane == 0) {
            for (int t = 0; t < 16; t++) {
                const int slot = t % 3, u = t / 3;
                if (u == 0) {
                    if (slot == 2) MBARRIER_WAIT_PARITY(mb_hdone, 0u);
                } else {
                    MBARRIER_WAIT_PARITY(mb_empty + slot*8, (u32)((u - 1) & 1));
                }
                MBARRIER_EXPECT_TX(mb_full + slot*8, 32768);
                BULK_G2S(sb + RING_B + slot*32768, (const char*)&g_B[t & 1][t >> 1][0],
                         32768, mb_full + slot*8);
            }
        }
    } else {
        // ================= 16 consumer warps =================
        compute_h(smf, smem, tid);
        __syncwarp();
        if (lane == 0) MBARRIER_ARRIVE(mb_hdone);   // W1/emb region (slot 2) free

        // warp = (wm 4) x (wn 2) x (wkt 2); tile m32 x n64 x k128(half)
        const int wm = wid >> 2, wn = (wid >> 1) & 1, wkt = wid & 1;
        const int m0 = wm * 32;
        const u32 aR0 = (u32)(m0 + (lane & 15));
        const u32 aX  = aR0 & 7;                       // (aR0+16)&7 == aR0&7
        const u32 aAddr0 = sb + HS_B + aR0 * 512;
        const u32 aAddr1 = aAddr0 + 16 * 512;
        const u32 aK  = (u32)(lane >> 4);
        const u32 bRow = (u32)(((lane >> 4) << 3) + (lane & 7));
        const u32 bK   = (u32)((lane >> 3) & 1);
        const u32 bX   = bRow & 7;
        const u32 bOff = bRow * 256 + (u32)(wn * 4) * 4096;
        const u32 kuBase = (u32)(wkt * 16);

        float acc[2][8][4];
        float fo[4][4], ft[4][4], fr[4][4][3];
        #pragma unroll
        for (int me = 0; me < 4; me++)
            #pragma unroll
            for (int q = 0; q < 4; q++) {
                fo[me][q] = 0.f; ft[me][q] = 0.f;
                fr[me][q][0] = 0.f; fr[me][q][1] = 0.f; fr[me][q][2] = 0.f;
            }

        for (int c = 0; c < 8; c++) {
            const int t = c * 2 + wkt;           // this warp's tile of chunk c
            const int slot = t % 3, u = t / 3;
            MBARRIER_WAIT_PARITY(mb_full + slot*8, (u32)(u & 1));

            #pragma unroll
            for (int mf = 0; mf < 2; mf++)
                #pragma unroll
                for (int nt = 0; nt < 8; nt++)
                    #pragma unroll
                    for (int q = 0; q < 4; q++) acc[mf][nt][q] = 0.f;

            const u32 ring = sb + RING_B + (u32)slot * 32768 + bOff;
            #pragma unroll
            for (int ks = 0; ks < 8; ks++) {
                u32 a0[4], a1[4];
                u32 ku = kuBase + (u32)(ks * 2) + aK;
                u32 swz = (ku & ~7u) | ((ku ^ aX) & 7u);
                ldsm4(a0, aAddr0 + (swz << 4));
                ldsm4(a1, aAddr1 + (swz << 4));
                u32 bu = ((u32)(ks * 2) + bK) ^ bX;
                #pragma unroll
                for (int pl = 0; pl < 4; pl++) {
                    u32 b[4];
                    ldsm4(b, ring + (bu << 4) + (u32)pl * 4096);
                    mma16816(acc[0][pl*2],     a0, b[0], b[1]);
                    mma16816(acc[0][pl*2 + 1], a0, b[2], b[3]);
                    mma16816(acc[1][pl*2],     a1, b[0], b[1]);
                    mma16816(acc[1][pl*2 + 1], a1, b[2], b[3]);
                }
            }
            __syncwarp();
            if (lane == 0) MBARRIER_ARRIVE(mb_empty + slot*8);   // done reading slot

            // ---- fold this warp's partial-w of chunk c into register finals ----
            {
                const int bsel = c >> 1;
                const int ibase = (c & 1) << 3;
                #pragma unroll
                for (int mf = 0; mf < 2; mf++) {
                    #pragma unroll
                    for (int ntl = 0; ntl < 8; ntl++) {
                        const int nt = wn * 8 + ntl;
                        const int i = ibase + wn * 4 + (ntl >> 1);
                        float b2v0 = 0.f, b2v1 = 0.f;
                        if (wkt == 0) {
                            const int nb = c * 128 + nt * 8 + (lane & 3) * 2;
                            b2v0 = smf[B2S_F + nb];
                            b2v1 = smf[B2S_F + nb + 1];
                        }
                        const int qb = (nt & 1) << 1;
                        #pragma unroll
                        for (int eh = 0; eh < 2; eh++) {
                            const int me = mf * 2 + eh;
                            const int e = m0 + mf * 16 + (lane >> 2) + eh * 8;
                            const float w0 = acc[mf][ntl][eh*2 + 0] + b2v0;
                            const float w1 = acc[mf][ntl][eh*2 + 1] + b2v1;
                            if (bsel == 0) {
                                float L = smf[LSS_F + e*16 + i];
                                fo[me][qb]   += L * w0;
                                fo[me][qb+1] += L * w1;
                            } else if (bsel == 1) {
                                float L = smf[LVV_F + e*16 + i];
                                fo[me][qb]   += L * w0;
                                fo[me][qb+1] += L * w1;
                            } else if (bsel == 2) {
                                float L = smf[LSV_F + e*16 + i];
                                ft[me][qb]   += L * w0;
                                ft[me][qb+1] += L * w1;
                            } else {
                                float L0 = smf[LVS_F + e*48 + i*3 + 0];
                                float L1 = smf[LVS_F + e*48 + i*3 + 1];
                                float L2 = smf[LVS_F + e*48 + i*3 + 2];
                                fr[me][qb][0]   += L0 * w0;
                                fr[me][qb][1]   += L1 * w0;
                                fr[me][qb][2]   += L2 * w0;
                                fr[me][qb+1][0] += L0 * w1;
                                fr[me][qb+1][1] += L1 * w1;
                                fr[me][qb+1][2] += L2 * w1;
                            }
                        }
                    }
                }
            }
        }

        // ---- final scatter: all (wn, wkt) partial owners add their shares ----
        #pragma unroll
        for (int me = 0; me < 4; me++) {
            const int e = m0 + (me >> 1) * 16 + (lane >> 2) + (me & 1) * 8;
            const int eg = eb + e;
            if (eg < E) {
                const int dst = edst[eg];
                float* ob = out + (size_t)dst * 64;
                const float y1a = smf[Y1_F + e*4 + 0];
                const float y1b = smf[Y1_F + e*4 + 1];
                const float y1c = smf[Y1_F + e*4 + 2];
                #pragma unroll
                for (int q = 0; q < 4; q++) {
                    const int j = ((q >> 1) << 3) + (lane & 3) * 2 + (q & 1);
                    atomicAdd(&ob[j], scl * fo[me][q]);
                    atomicAdd(&ob[16 + j*3 + 0], scl * (ft[me][q] * y1a + fr[me][q][0]));
                    atomicAdd(&ob[16 + j*3 + 1], scl * (ft[me][q] * y1b + fr[me][q][1]));
                    atomicAdd(&ob[16 + j*3 + 2], scl * (ft[me][q] * y1c + fr[me][q][2]));
                }
            }
        }
    }
}

extern "C" void kernel_launch(void* const* d_in, const int* in_sizes, int n_in,
                              void* d_out, int out_size) {
    const float* nodef = (const float*)d_in[0];
    const float* eattr = (const float*)d_in[1];
    const float* eemb  = (const float*)d_in[2];
    const float* W1    = (const float*)d_in[3];
    const float* b1    = (const float*)d_in[4];
    const float* W2    = (const float*)d_in[5];
    const float* b2    = (const float*)d_in[6];
    const int*   esrc  = (const int*)d_in[7];
    const int*   edst  = (const int*)d_in[8];
    float* out = (float*)d_out;

    int E  = in_sizes[7];
    int Nn = out_size / 64;
    const float cS = 0.17677669529663688110f;  // sqrt(1/32)
    float scl = cS / sqrtf((float)E / (float)Nn);

    cudaMemsetAsync(d_out, 0, (size_t)out_size * sizeof(float));
    prep_w2<<<1024, 256>>>(W2);

    cudaFuncSetAttribute(nequip_mma, cudaFuncAttributeMaxDynamicSharedMemorySize, SMEM_BYTES);
    int grid = (E + TE - 1) / TE;
    nequip_mma<<<grid, 544, SMEM_BYTES>>>(nodef, eattr, eemb, W1, b1, b2,
                                          esrc, edst, out, E, scl);
}

// round 16
// speedup vs baseline: 1.2385x; 1.2385x over previous
#include <cuda_runtime.h>
#include <cuda_fp16.h>
#include <math.h>

typedef unsigned u32;
typedef unsigned long long u64;

#define TE 128

// Pre-swizzled fp16 W2 tile images: [ktile(2)][chunk(8)][128n x 128k fp16 = 32KB]
__device__ __align__(16) __half g_B[2][8][16384];

// ---------------- helpers ----------------
__device__ __forceinline__ u32 smem_u32(const void* p) {
    u32 a; asm("{ .reg .u64 t; cvta.to.shared.u64 t, %1; cvt.u32.u64 %0, t; }" : "=r"(a) : "l"(p));
    return a;
}
__device__ __forceinline__ void cp16(u32 dst, const void* src) {
    asm volatile("cp.async.cg.shared.global [%0], [%1], 16;" :: "r"(dst), "l"(src));
}
__device__ __forceinline__ void cp_commit() { asm volatile("cp.async.commit_group;"); }
template<int N> __device__ __forceinline__ void cp_wait() {
    asm volatile("cp.async.wait_group %0;" :: "n"(N));
}
__device__ __forceinline__ void ldsm4(u32* r, u32 addr) {
    asm volatile("ldmatrix.sync.aligned.m8n8.x4.shared.b16 {%0,%1,%2,%3}, [%4];"
        : "=r"(r[0]), "=r"(r[1]), "=r"(r[2]), "=r"(r[3]) : "r"(addr));
}
__device__ __forceinline__ void mma16816(float* d, const u32* a, u32 b0, u32 b1) {
    asm volatile("mma.sync.aligned.m16n8k16.row.col.f32.f16.f16.f32 "
        "{%0,%1,%2,%3}, {%4,%5,%6,%7}, {%8,%9}, {%0,%1,%2,%3};"
        : "+f"(d[0]), "+f"(d[1]), "+f"(d[2]), "+f"(d[3])
        : "r"(a[0]), "r"(a[1]), "r"(a[2]), "r"(a[3]), "r"(b0), "r"(b1));
}
// vector global reduction (sm_90+ base): 8B-aligned destination required
__device__ __forceinline__ void red2(float* addr, float a, float b) {
    asm volatile("red.global.add.v2.f32 [%0], {%1, %2};" :: "l"(addr), "f"(a), "f"(b) : "memory");
}

// ---------------- smem layout ----------------
// bytes:
#define RING_B 0          // 3 slots x 32768
#define HS_B   98304      // A image: 128 edges x 256 k fp16 = 64KB (512B rows)
// transient constants alias ring slot 2 (base byte 65536 = float 16384):
#define W1S_F  16384      // [18][256]
#define B1S_F  20992      // 256
#define EMBS_F 21248      // 128*18
// persistent floats after HS (byte 163840 = float 40960)
#define B2S_F  40960      // 1024
#define LSS_F  41984      // 128*16
#define LVV_F  44032
#define LSV_F  46080
#define LVS_F  48128      // 128*48
#define Y1_F   54272      // 128*4
#define SMEM_BYTES 219136

// ---------------- prep: fp16 convert + swizzle W2 ----------------
__global__ void prep_w2(const float* __restrict__ W2) {
    int idx = blockIdx.x * blockDim.x + threadIdx.x;
    if (idx >= 256 * 1024) return;
    int k = idx >> 10, n = idx & 1023;
    __half v = __float2half(W2[idx]);
    int kt = k >> 7, kl = k & 127, chunk = n >> 7, nl = n & 127;
    int off = nl * 256 + (((kl >> 3) ^ (nl & 7)) << 4) + (kl & 7) * 2;  // bytes
    g_B[kt][chunk][off >> 1] = v;
}

// ---------------- h compute (full K=256, fp16 out, 512 threads) ----------------
__device__ __forceinline__ void compute_h(float* smf, char* smem, int tid) {
    const int e = tid & 127;
    const int qt = tid >> 7;           // column quarter (64 cols each)
    float er[18];
    #pragma unroll
    for (int t = 0; t < 18; t++) er[t] = smf[EMBS_F + e * 18 + t];
    const int cbase = qt * 64;
    #pragma unroll 2
    for (int cc = 0; cc < 64; cc += 2) {
        const int c = cbase + cc;              // k in [0,256)
        float h[2];
        #pragma unroll
        for (int u = 0; u < 2; u++) {
            float a = smf[B1S_F + c + u];
            #pragma unroll
            for (int t = 0; t < 18; t++)
                a = fmaf(er[t], smf[W1S_F + t * 256 + c + u], a);
            h[u] = a / (1.f + __expf(-a));
        }
        __half2 hp; hp.x = __float2half(h[0]); hp.y = __float2half(h[1]);
        u32 off = (u32)(e * 512 + (((c >> 3) ^ (e & 7)) << 4) + (c & 7) * 2);
        *(u32*)(smem + HS_B + off) = *(u32*)&hp;
    }
}

// prefetch one B tile tt into ring slot (tt % 3)
__device__ __forceinline__ void prefetch_tile(u32 sb, int tt, int tid) {
    const char* src = (const char*)&g_B[tt & 1][tt >> 1][0];
    const u32 dst = sb + RING_B + ((u32)(tt % 3)) * 32768;
    #pragma unroll
    for (int jj = 0; jj < 4; jj++) {
        int seg = tid + 512 * jj;
        cp16(dst + seg * 16, src + seg * 16);
    }
    cp_commit();
}

// ---------------- main kernel: 16 warps, tile m32 x n32 (4m x 4n) ----------------
__global__ __launch_bounds__(512, 1)
void nequip_mma(const float* __restrict__ nodef,
                const float* __restrict__ eattr,
                const float* __restrict__ eemb,
                const float* __restrict__ W1,
                const float* __restrict__ bias1,
                const float* __restrict__ b2,
                const int* __restrict__ esrc,
                const int* __restrict__ edst,
                float* __restrict__ out,
                int E, float scl)
{
    extern __shared__ char smem[];
    float* smf = (float*)smem;
    const u32 sb = smem_u32(smem);
    const int tid = threadIdx.x;
    const int wid = tid >> 5, lane = tid & 31;
    const int wgtid = tid & 127, wg = tid >> 7;
    const int eb = blockIdx.x * TE;

    // ---- stage constants via cp.async (W1/b1/emb alias ring slot 2) ----
    {
        const u32 w1dst = sb + W1S_F * 4;
        #pragma unroll
        for (int i = tid; i < 1152; i += 512) cp16(w1dst + i * 16, (const char*)W1 + i * 16);
        if (tid < 64) cp16(sb + B1S_F * 4 + tid * 16, (const char*)bias1 + tid * 16);
        if (tid >= 256 && tid < 512) {
            int i = tid - 256;
            cp16(sb + B2S_F * 4 + i * 16, (const char*)b2 + i * 16);
        }
        if (eb + TE <= E) {
            const u32 emdst = sb + EMBS_F * 4;
            const char* emsrc = (const char*)(eemb + (size_t)eb * 18);
            #pragma unroll
            for (int i = tid; i < 576; i += 512) cp16(emdst + i * 16, emsrc + i * 16);
        } else {
            for (int i = tid; i < TE * 18; i += 512) {
                int g = eb * 18 + i;
                smf[EMBS_F + i] = (g < E * 18) ? eemb[g] : 0.f;
            }
        }
        cp_commit();
        prefetch_tile(sb, 0, tid);     // slot 0
        prefetch_tile(sb, 1, tid);     // slot 1
    }

    // ---- per-edge left vectors (4 groups of 4 i's) ----
    {
        const int eg = eb + wgtid;
        if (eg < E) {
            const float inv3 = 0.57735026918962576451f;
            int src = esrc[eg];
            const float* x = nodef + (size_t)src * 64;
            float4 ya = *(const float4*)(eattr + (size_t)eg * 4);
            if (wg == 0) {
                smf[Y1_F + wgtid*4 + 0] = ya.y;
                smf[Y1_F + wgtid*4 + 1] = ya.z;
                smf[Y1_F + wgtid*4 + 2] = ya.w;
            }
            float4 sv = *(const float4*)(x + wg * 4);
            float s4[4] = {sv.x, sv.y, sv.z, sv.w};
            float vv[12];
            const float4* vx = (const float4*)(x + 16 + wg * 12);
            #pragma unroll
            for (int q = 0; q < 3; q++) {
                float4 t = vx[q];
                vv[q*4] = t.x; vv[q*4+1] = t.y; vv[q*4+2] = t.z; vv[q*4+3] = t.w;
            }
            #pragma unroll
            for (int il = 0; il < 4; il++) {
                int i = wg * 4 + il;
                smf[LSS_F + wgtid*16 + i] = ya.x * s4[il];
                smf[LSV_F + wgtid*16 + i] = s4[il];
                smf[LVV_F + wgtid*16 + i] =
                    inv3 * (ya.y*vv[il*3] + ya.z*vv[il*3+1] + ya.w*vv[il*3+2]);
                smf[LVS_F + wgtid*48 + i*3 + 0] = ya.x * vv[il*3 + 0];
                smf[LVS_F + wgtid*48 + i*3 + 1] = ya.x * vv[il*3 + 1];
                smf[LVS_F + wgtid*48 + i*3 + 2] = ya.x * vv[il*3 + 2];
            }
        }
    }

    cp_wait<2>();           // constants group done (tiles 0,1 may be in flight)
    __syncthreads();
    compute_h(smf, smem, tid);

    // ---- per-lane state: warp = (wm 4) x (wn2 4); tile m32 x n32 ----
    const int wm = wid >> 2, wn2 = wid & 3;
    const int m0 = wm * 32;
    const u32 aR0 = (u32)(m0 + (lane & 15));
    const u32 aX  = aR0 & 7;                       // (aR0+16)&7 == aR0&7
    const u32 aAddr0 = sb + HS_B + aR0 * 512;
    const u32 aAddr1 = aAddr0 + 16 * 512;
    const u32 aK   = (u32)(lane >> 4);
    const u32 bRow = (u32)(((lane >> 4) << 3) + (lane & 7));
    const u32 bK   = (u32)((lane >> 3) & 1);
    const u32 bX   = bRow & 7;
    const u32 bOff = bRow * 256 + (u32)(wn2 * 2) * 4096;   // n-offset = wn2*32 cols

    float acc[2][4][4];
    float fo[4][4], fr[4][4][3];
    #pragma unroll
    for (int me = 0; me < 4; me++)
        #pragma unroll
        for (int q = 0; q < 4; q++) {
            fo[me][q] = 0.f;
            fr[me][q][0] = 0.f; fr[me][q][1] = 0.f; fr[me][q][2] = 0.f;
        }

    // ---- main loop: 16 tiles (chunk*2 + kt), 3-stage ring ----
    for (int t = 0; t < 16; t++) {
        const int kt = t & 1;
        cp_wait<1>();                    // tile t landed (t+1 may be in flight)
        __syncthreads();                 // slot (t+2)%3 readers (phase t-1) done
        if (t + 2 < 16) prefetch_tile(sb, t + 2, tid);

        if (kt == 0) {
            #pragma unroll
            for (int mf = 0; mf < 2; mf++)
                #pragma unroll
                for (int nt = 0; nt < 4; nt++)
                    #pragma unroll
                    for (int q = 0; q < 4; q++) acc[mf][nt][q] = 0.f;
        }

        const u32 ring = sb + RING_B + ((u32)(t % 3)) * 32768 + bOff;
        #pragma unroll
        for (int ks = 0; ks < 8; ks++) {
            u32 a0[4], a1[4];
            u32 ku = (u32)(kt * 16 + ks * 2) + aK;
            u32 swz = (ku & ~7u) | ((ku ^ aX) & 7u);
            ldsm4(a0, aAddr0 + (swz << 4));
            ldsm4(a1, aAddr1 + (swz << 4));
            u32 bu = ((u32)(ks * 2) + bK) ^ bX;
            #pragma unroll
            for (int pl = 0; pl < 2; pl++) {
                u32 b[4];
                ldsm4(b, ring + (bu << 4) + (u32)pl * 4096);
                mma16816(acc[0][pl*2],     a0, b[0], b[1]);
                mma16816(acc[0][pl*2 + 1], a0, b[2], b[3]);
                mma16816(acc[1][pl*2],     a1, b[0], b[1]);
                mma16816(acc[1][pl*2 + 1], a1, b[2], b[3]);
            }
        }

        if (kt == 1) {
            // ---- fold chunk into register finals (lane-local) ----
            const int c = t >> 1;
            const int bsel = c >> 1;
            const int ibase = (c & 1) << 3;
            #pragma unroll
            for (int mf = 0; mf < 2; mf++) {
                #pragma unroll
                for (int ntl = 0; ntl < 4; ntl++) {
                    const int nt = wn2 * 4 + ntl;
                    const int i = ibase + (nt >> 1);
                    const int nb = c * 128 + nt * 8 + (lane & 3) * 2;
                    const float b2v0 = smf[B2S_F + nb];
                    const float b2v1 = smf[B2S_F + nb + 1];
                    const int qb = (nt & 1) << 1;
                    #pragma unroll
                    for (int eh = 0; eh < 2; eh++) {
                        const int me = mf * 2 + eh;
                        const int e = m0 + mf * 16 + (lane >> 2) + eh * 8;
                        const float w0 = acc[mf][ntl][eh*2 + 0] + b2v0;
                        const float w1 = acc[mf][ntl][eh*2 + 1] + b2v1;
                        if (bsel == 0) {
                            float L = smf[LSS_F + e*16 + i];
                            fo[me][qb]   += L * w0;
                            fo[me][qb+1] += L * w1;
                        } else if (bsel == 1) {
                            float L = smf[LVV_F + e*16 + i];
                            fo[me][qb]   += L * w0;
                            fo[me][qb+1] += L * w1;
                        } else if (bsel == 2) {
                            // fold Lsv*y1_a directly into fr (out_v = sum (Lsv y1_a + Lvs_a) w)
                            float L = smf[LSV_F + e*16 + i];
                            float L0 = L * smf[Y1_F + e*4 + 0];
                            float L1 = L * smf[Y1_F + e*4 + 1];
                            float L2 = L * smf[Y1_F + e*4 + 2];
                            fr[me][qb][0]   += L0 * w0;
                            fr[me][qb][1]   += L1 * w0;
                            fr[me][qb][2]   += L2 * w0;
                            fr[me][qb+1][0] += L0 * w1;
                            fr[me][qb+1][1] += L1 * w1;
                            fr[me][qb+1][2] += L2 * w1;
                        } else {
                            float L0 = smf[LVS_F + e*48 + i*3 + 0];
                            float L1 = smf[LVS_F + e*48 + i*3 + 1];
                            float L2 = smf[LVS_F + e*48 + i*3 + 2];
                            fr[me][qb][0]   += L0 * w0;
                            fr[me][qb][1]   += L1 * w0;
                            fr[me][qb][2]   += L2 * w0;
                            fr[me][qb+1][0] += L0 * w1;
                            fr[me][qb+1][1] += L1 * w1;
                            fr[me][qb+1][2] += L2 * w1;
                        }
                    }
                }
            }
        }
    }

    // ---- final scatter: vectorized global reductions (8B-aligned pairs) ----
    #pragma unroll
    for (int me = 0; me < 4; me++) {
        const int e = m0 + (me >> 1) * 16 + (lane >> 2) + (me & 1) * 8;
        const int eg = eb + e;
        if (eg < E) {
            const int dst = edst[eg];
            float* ob = out + (size_t)dst * 64;
            const int j0 = (lane & 3) * 2;
            // out_s: j0, j0+1 and 8+j0, 8+j0+1
            red2(&ob[j0],     scl * fo[me][0], scl * fo[me][1]);
            red2(&ob[8 + j0], scl * fo[me][2], scl * fo[me][3]);
            // out_v: q0/q1 -> j = j0, j0+1 : 6 contiguous floats at 16+3*j0
            float* p = &ob[16 + 3 * j0];
            red2(p + 0, scl * fr[me][0][0], scl * fr[me][0][1]);
            red2(p + 2, scl * fr[me][0][2], scl * fr[me][1][0]);
            red2(p + 4, scl * fr[me][1][1], scl * fr[me][1][2]);
            // out_v: q2/q3 -> j = 8+j0, 8+j0+1 : 6 floats at 16+3*(8+j0) = 40+3*j0
            float* p2 = &ob[40 + 3 * j0];
            red2(p2 + 0, scl * fr[me][2][0], scl * fr[me][2][1]);
            red2(p2 + 2, scl * fr[me][2][2], scl * fr[me][3][0]);
            red2(p2 + 4, scl * fr[me][3][1], scl * fr[me][3][2]);
        }
    }
}

extern "C" void kernel_launch(void* const* d_in, const int* in_sizes, int n_in,
                              void* d_out, int out_size) {
    const float* nodef = (const float*)d_in[0];
    const float* eattr = (const float*)d_in[1];
    const float* eemb  = (const float*)d_in[2];
    const float* W1    = (const float*)d_in[3];
    const float* b1    = (const float*)d_in[4];
    const float* W2    = (const float*)d_in[5];
    const float* b2    = (const float*)d_in[6];
    const int*   esrc  = (const int*)d_in[7];
    const int*   edst  = (const int*)d_in[8];
    float* out = (float*)d_out;

    int E  = in_sizes[7];
    int Nn = out_size / 64;
    const float cS = 0.17677669529663688110f;  // sqrt(1/32)
    float scl = cS / sqrtf((float)E / (float)Nn);

    cudaMemsetAsync(d_out, 0, (size_t)out_size * sizeof(float));
    prep_w2<<<1024, 256>>>(W2);

    cudaFuncSetAttribute(nequip_mma, cudaFuncAttributeMaxDynamicSharedMemorySize, SMEM_BYTES);
    int grid = (E + TE - 1) / TE;
    nequip_mma<<<grid, 512, SMEM_BYTES>>>(nodef, eattr, eemb, W1, b1, b2,
                                          esrc, edst, out, E, scl);
}